// round 10
// baseline (speedup 1.0000x reference)
#include <cuda_runtime.h>
#include <cuda_bf16.h>
#include <cstdint>
#include <math.h>

#define NN 50000
#define NE 800000
#define FIN 512
#define HD1 64
#define HD2 128
#define NG 64
#define NC 10

// ---------------- scratch (device globals; no runtime allocation) -------------
__device__ __align__(16) float    g_buf1[(size_t)NN * 128]; // GEMM1 out [y_l|y_r]; reused as h2
__device__ __align__(16) float    g_buf2[(size_t)NN * 128]; // layer-2 GEMM input [mean_h|h]
__device__ __align__(16) float    g_h   [(size_t)NN * 64];  // layer-1 activations
__device__ __align__(16) unsigned g_B1  [512 * 128];        // packed tf32 [w1_l | w1_r]
__device__ __align__(16) unsigned g_B2  [128 * 128];        // packed tf32 [[w2_l];[w2_r]]
__device__ int      g_deg [NN];
__device__ int      g_rowstart[NN + 1];
__device__ int      g_cursor[NN];
__device__ int      g_csrsrc[NE];
__device__ float    g_pooled[NG * HD2];
__device__ int      g_cnt [NG];
__device__ int      g_is64;   // 1 if edge_index/batch are int64, 0 if int32

__device__ __forceinline__ unsigned f2tf32(float x) {
    unsigned r;
    asm("cvt.rna.tf32.f32 %0, %1;" : "=r"(r) : "f"(x));
    return r;
}

// ---------------- dtype detect: int64 little-endian => odd int32 words all 0 ---
__global__ void k_detect(const int* __restrict__ ei) {
    if (threadIdx.x == 0) {
        int odd_or = 0;
        for (int i = 0; i < 256; i++) odd_or |= ei[2 * i + 1];
        g_is64 = (odd_or == 0) ? 1 : 0;
    }
}

__device__ __forceinline__ int clampN(int v, int n) {
    return (v < 0) ? 0 : (v >= n ? n - 1 : v);
}

// ---------------- zero accumulators -------------------------------------------
__global__ void k_zero() {
    int i = blockIdx.x * 256 + threadIdx.x;
    if (i < NN)        g_deg[i] = 0;
    if (i < NG * HD2)  g_pooled[i] = 0.f;
    if (i < NG)        g_cnt[i] = 0;
}

// ---------------- pack weights (concat + tf32 convert) ------------------------
__global__ void k_packB1(const float* __restrict__ wl, const float* __restrict__ wr) {
    int i = blockIdx.x * 256 + threadIdx.x;
    if (i >= 512 * 128) return;
    int k = i >> 7, j = i & 127;
    float v = (j < 64) ? wl[k * 64 + j] : wr[k * 64 + (j - 64)];
    g_B1[i] = f2tf32(v);
}
__global__ void k_packB2(const float* __restrict__ wl, const float* __restrict__ wr) {
    int i = blockIdx.x * 256 + threadIdx.x;
    if (i >= 128 * 128) return;
    int k = i >> 7, j = i & 127;
    float v = (k < 64) ? wl[k * 128 + j] : wr[(k - 64) * 128 + j];
    g_B2[i] = f2tf32(v);
}

// ---------------- CSR build (dtype-agnostic index loads) -----------------------
__device__ __forceinline__ int load_src(const int* ei, int e, int is64) {
    return is64 ? ei[2 * e] : ei[e];
}
__device__ __forceinline__ int load_dst(const int* ei, int e, int is64) {
    return is64 ? ei[2 * (NE + e)] : ei[NE + e];
}

__global__ void k_deg(const int* __restrict__ ei) {
    int e = blockIdx.x * 256 + threadIdx.x;
    if (e >= NE) return;
    int is64 = g_is64;
    int d = clampN(load_dst(ei, e, is64), NN);
    atomicAdd(&g_deg[d], 1);
}

__global__ void k_scan() {
    __shared__ int sums[1024];
    const int t = threadIdx.x;
    const int chunk = (NN + 1023) >> 10;          // 49
    int beg = t * chunk, end = beg + chunk;
    if (end > NN) end = NN;
    if (beg > NN) beg = NN;
    int s = 0;
    for (int i = beg; i < end; i++) s += g_deg[i];
    sums[t] = s;
    __syncthreads();
    for (int off = 1; off < 1024; off <<= 1) {
        int v = (t >= off) ? sums[t - off] : 0;
        __syncthreads();
        sums[t] += v;
        __syncthreads();
    }
    int run = sums[t] - s;                        // exclusive prefix for this chunk
    for (int i = beg; i < end; i++) {
        g_rowstart[i] = run;
        g_cursor[i]   = run;
        run += g_deg[i];
    }
    if (t == 1023) g_rowstart[NN] = sums[1023];
}

__global__ void k_fill(const int* __restrict__ ei) {
    int e = blockIdx.x * 256 + threadIdx.x;
    if (e >= NE) return;
    int is64 = g_is64;
    int s = clampN(load_src(ei, e, is64), NN);
    int d = clampN(load_dst(ei, e, is64), NN);
    int pos = atomicAdd(&g_cursor[d], 1);
    if (pos >= 0 && pos < NE) g_csrsrc[pos] = s;
}

// ---------------- tf32 tensor-core GEMM:  C[M,128] = A[M,K] @ B[K,128] (+bias) -
// BM=128, BN=128, BK=32, 256 threads, warp tile 32x64 (2x8 m16n8k8 tiles).
template <int K>
__global__ __launch_bounds__(256)
void gemm_tf32(const float* __restrict__ A, const unsigned* __restrict__ B,
               const float* __restrict__ bias, float* __restrict__ C, int M) {
    __shared__ __align__(16) unsigned As[32][136];   // [k][m]
    __shared__ __align__(16) unsigned Bs[32][136];   // [k][n]

    const int tid  = threadIdx.x;
    const int wid  = tid >> 5;
    const int lane = tid & 31;
    const int g    = lane >> 2;        // group id (0..7)
    const int t    = lane & 3;         // thread-in-group (0..3)
    const int warpM = wid & 3, warpN = wid >> 2;
    const int rowBase = warpM * 32, colBase = warpN * 64;
    const int blockRow = blockIdx.x * 128;

    float acc[2][8][4];
#pragma unroll
    for (int mi = 0; mi < 2; mi++)
#pragma unroll
        for (int ni = 0; ni < 8; ni++)
#pragma unroll
            for (int r = 0; r < 4; r++) acc[mi][ni][r] = 0.f;

    for (int kt = 0; kt < K; kt += 32) {
        // stage A (transposed to [k][m]); per warp: fixed k-quad, 32 rows
#pragma unroll
        for (int p = 0; p < 4; p++) {
            int r  = lane + p * 32;
            int gr = blockRow + r;
            if (gr >= M) gr = M - 1;               // clamp: tail rows never stored
            float4 v = *(const float4*)(A + (size_t)gr * K + kt + wid * 4);
            As[wid * 4 + 0][r] = f2tf32(v.x);
            As[wid * 4 + 1][r] = f2tf32(v.y);
            As[wid * 4 + 2][r] = f2tf32(v.z);
            As[wid * 4 + 3][r] = f2tf32(v.w);
        }
        // stage B: coalesced rows of 128 uints
#pragma unroll
        for (int p = 0; p < 4; p++) {
            int kr = wid + p * 8;
            uint4 v = *(const uint4*)(B + (size_t)(kt + kr) * 128 + lane * 4);
            *(uint4*)&Bs[kr][lane * 4] = v;
        }
        __syncthreads();

#pragma unroll
        for (int kk = 0; kk < 4; kk++) {
            const int k0 = kk * 8;
            unsigned a[2][4];
#pragma unroll
            for (int mi = 0; mi < 2; mi++) {
                int r = rowBase + mi * 16 + g;
                a[mi][0] = As[k0 + t][r];
                a[mi][1] = As[k0 + t][r + 8];
                a[mi][2] = As[k0 + t + 4][r];
                a[mi][3] = As[k0 + t + 4][r + 8];
            }
            unsigned b[8][2];
#pragma unroll
            for (int ni = 0; ni < 8; ni++) {
                int c = colBase + ni * 8 + g;
                b[ni][0] = Bs[k0 + t][c];
                b[ni][1] = Bs[k0 + t + 4][c];
            }
#pragma unroll
            for (int mi = 0; mi < 2; mi++)
#pragma unroll
                for (int ni = 0; ni < 8; ni++)
                    asm volatile(
                        "mma.sync.aligned.m16n8k8.row.col.f32.tf32.tf32.f32 "
                        "{%0,%1,%2,%3}, {%4,%5,%6,%7}, {%8,%9}, {%0,%1,%2,%3};\n"
                        : "+f"(acc[mi][ni][0]), "+f"(acc[mi][ni][1]),
                          "+f"(acc[mi][ni][2]), "+f"(acc[mi][ni][3])
                        : "r"(a[mi][0]), "r"(a[mi][1]), "r"(a[mi][2]), "r"(a[mi][3]),
                          "r"(b[ni][0]), "r"(b[ni][1]));
        }
        __syncthreads();
    }

    // epilogue
#pragma unroll
    for (int mi = 0; mi < 2; mi++) {
        int r0 = blockRow + rowBase + mi * 16 + g;
#pragma unroll
        for (int ni = 0; ni < 8; ni++) {
            int c = colBase + ni * 8 + 2 * t;
            float bx = 0.f, by = 0.f;
            if (bias) { bx = bias[c]; by = bias[c + 1]; }
            if (r0 < M)
                *(float2*)(C + (size_t)r0 * 128 + c) =
                    make_float2(acc[mi][ni][0] + bx, acc[mi][ni][1] + by);
            if (r0 + 8 < M)
                *(float2*)(C + (size_t)(r0 + 8) * 128 + c) =
                    make_float2(acc[mi][ni][2] + bx, acc[mi][ni][3] + by);
        }
    }
}

// ---------------- layer-1 combine: h = relu(mean(agg y_l) + b1 + y_r) ----------
__global__ void k_agg1(const float* __restrict__ y, const float* __restrict__ b1,
                       float* __restrict__ h) {
    int node = blockIdx.x * 8 + (threadIdx.x >> 5);
    if (node >= NN) return;
    int lane = threadIdx.x & 31;
    int beg = g_rowstart[node], end = g_rowstart[node + 1];
    float ax = 0.f, ay = 0.f;
    for (int e = beg; e < end; e++) {
        int s = g_csrsrc[e];
        float2 v = *(const float2*)(y + (size_t)s * 128 + 2 * lane);
        ax += v.x; ay += v.y;
    }
    float inv = 1.f / fmaxf((float)(end - beg), 1.f);
    float2 yr = *(const float2*)(y + (size_t)node * 128 + 64 + 2 * lane);
    float b0 = b1[2 * lane], b1v = b1[2 * lane + 1];
    float o0 = fmaxf(ax * inv + b0 + yr.x, 0.f);
    float o1 = fmaxf(ay * inv + b1v + yr.y, 0.f);
    *(float2*)(h + (size_t)node * 64 + 2 * lane) = make_float2(o0, o1);
}

// ---------------- layer-2 input: g = [mean(agg h) | h] -------------------------
__global__ void k_agg2(const float* __restrict__ h, float* __restrict__ gbuf) {
    int node = blockIdx.x * 8 + (threadIdx.x >> 5);
    if (node >= NN) return;
    int lane = threadIdx.x & 31;
    int beg = g_rowstart[node], end = g_rowstart[node + 1];
    float ax = 0.f, ay = 0.f;
    for (int e = beg; e < end; e++) {
        int s = g_csrsrc[e];
        float2 v = *(const float2*)(h + (size_t)s * 64 + 2 * lane);
        ax += v.x; ay += v.y;
    }
    float inv = 1.f / fmaxf((float)(end - beg), 1.f);
    float2 hv = *(const float2*)(h + (size_t)node * 64 + 2 * lane);
    *(float2*)(gbuf + (size_t)node * 128 + 2 * lane)      = make_float2(ax * inv, ay * inv);
    *(float2*)(gbuf + (size_t)node * 128 + 64 + 2 * lane) = hv;
}

// ---------------- global mean pool (batch is sorted) ---------------------------
__global__ void k_pool(const float* __restrict__ h2, const int* __restrict__ batch) {
    int f = threadIdx.x;                    // 128 features
    int is64 = g_is64;
    int start = blockIdx.x * 128;
    int end = start + 128; if (end > NN) end = NN;
    float acc = 0.f;
    int cur = -1, cl = 0;
    for (int i = start; i < end; i++) {
        int gg = clampN(is64 ? batch[2 * i] : batch[i], NG);
        if (gg != cur) {
            if (cur >= 0) {
                atomicAdd(&g_pooled[cur * 128 + f], acc);
                if (f == 0) atomicAdd(&g_cnt[cur], cl);
            }
            cur = gg; acc = 0.f; cl = 0;
        }
        acc += h2[(size_t)i * 128 + f];
        cl++;
    }
    if (cur >= 0) {
        atomicAdd(&g_pooled[cur * 128 + f], acc);
        if (f == 0) atomicAdd(&g_cnt[cur], cl);
    }
}

// ---------------- final FC + log_softmax --------------------------------------
__global__ void k_final(const float* __restrict__ wfc, const float* __restrict__ bfc,
                        float* __restrict__ out) {
    int gi = threadIdx.x;
    if (gi >= NG) return;
    float invc = 1.f / fmaxf((float)g_cnt[gi], 1.f);
    float z[NC];
#pragma unroll
    for (int c = 0; c < NC; c++) z[c] = bfc[c];
    for (int k = 0; k < HD2; k++) {
        float p = g_pooled[gi * HD2 + k] * invc;
#pragma unroll
        for (int c = 0; c < NC; c++) z[c] += p * wfc[k * NC + c];
    }
    float m = z[0];
#pragma unroll
    for (int c = 1; c < NC; c++) m = fmaxf(m, z[c]);
    float s = 0.f;
#pragma unroll
    for (int c = 0; c < NC; c++) s += expf(z[c] - m);
    float lse = m + logf(s);
#pragma unroll
    for (int c = 0; c < NC; c++) out[gi * NC + c] = z[c] - lse;
}

// ---------------- launch -------------------------------------------------------
extern "C" void kernel_launch(void* const* d_in, const int* in_sizes, int n_in,
                              void* d_out, int out_size) {
    const float* x     = (const float*)d_in[0];
    const int*   ei    = (const int*)d_in[1];    // int32 OR int64 (runtime-detected)
    const int*   batch = (const int*)d_in[2];    // same dtype as ei
    const float* w1l   = (const float*)d_in[3];
    const float* b1    = (const float*)d_in[4];
    const float* w1r   = (const float*)d_in[5];
    const float* w2l   = (const float*)d_in[6];
    const float* b2    = (const float*)d_in[7];
    const float* w2r   = (const float*)d_in[8];
    const float* wfc   = (const float*)d_in[9];
    const float* bfc   = (const float*)d_in[10];
    float* out = (float*)d_out;

    float *buf1, *buf2, *hbuf;
    unsigned *B1, *B2;
    cudaGetSymbolAddress((void**)&buf1, g_buf1);
    cudaGetSymbolAddress((void**)&buf2, g_buf2);
    cudaGetSymbolAddress((void**)&hbuf, g_h);
    cudaGetSymbolAddress((void**)&B1,   g_B1);
    cudaGetSymbolAddress((void**)&B2,   g_B2);

    k_detect<<<1, 32>>>(ei);
    k_zero<<<(NN + 255) / 256, 256>>>();
    k_packB1<<<(512 * 128 + 255) / 256, 256>>>(w1l, w1r);
    k_packB2<<<(128 * 128 + 255) / 256, 256>>>(w2l, w2r);
    k_deg<<<(NE + 255) / 256, 256>>>(ei);
    k_scan<<<1, 1024>>>();
    k_fill<<<(NE + 255) / 256, 256>>>(ei);

    gemm_tf32<512><<<(NN + 127) / 128, 256>>>(x, B1, nullptr, buf1, NN);
    k_agg1<<<(NN + 7) / 8, 256>>>(buf1, b1, hbuf);
    k_agg2<<<(NN + 7) / 8, 256>>>(hbuf, buf2);
    gemm_tf32<128><<<(NN + 127) / 128, 256>>>(buf2, B2, b2, buf1, NN);

    k_pool<<<(NN + 127) / 128, 128>>>(buf1, batch);
    k_final<<<1, 64>>>(wfc, bfc, out);
}

// round 11
// speedup vs baseline: 1.0778x; 1.0778x over previous
#include <cuda_runtime.h>
#include <cuda_bf16.h>
#include <cstdint>
#include <math.h>

#define NN 50000
#define NE 800000
#define FIN 512
#define HD1 64
#define HD2 128
#define NG 64
#define NC 10

// ---------------- scratch (device globals; no runtime allocation) -------------
__device__ __align__(16) float    g_buf1[(size_t)NN * 128]; // GEMM1 out [y_l|y_r]; reused as h2
__device__ __align__(16) float    g_buf2[(size_t)NN * 128]; // layer-2 GEMM input [mean_h|h]
__device__ __align__(16) float    g_h   [(size_t)NN * 64];  // layer-1 activations
__device__ __align__(16) unsigned g_B1  [512 * 128];        // packed tf32 [w1_l | w1_r]
__device__ __align__(16) unsigned g_B2  [128 * 128];        // packed tf32 [[w2_l];[w2_r]]
__device__ int      g_deg [NN];
__device__ int      g_rowstart[NN + 1];
__device__ int      g_cursor[NN];
__device__ int      g_csrsrc[NE];
__device__ float    g_pooled[NG * HD2];
__device__ int      g_cnt [NG];
__device__ int      g_is64;   // 1 if edge_index/batch are int64, 0 if int32

__device__ __forceinline__ unsigned f2tf32(float x) {
    unsigned r;
    asm("cvt.rna.tf32.f32 %0, %1;" : "=r"(r) : "f"(x));
    return r;
}
__device__ __forceinline__ unsigned u2tf32(unsigned ub) {
    unsigned r; float f = __uint_as_float(ub);
    asm("cvt.rna.tf32.f32 %0, %1;" : "=r"(r) : "f"(f));
    return r;
}
__device__ __forceinline__ void cp16(unsigned* dst_smem, const void* src) {
    unsigned d = (unsigned)__cvta_generic_to_shared(dst_smem);
    asm volatile("cp.async.cg.shared.global [%0], [%1], 16;" :: "r"(d), "l"(src) : "memory");
}
__device__ __forceinline__ int clampN(int v, int n) {
    return (v < 0) ? 0 : (v >= n ? n - 1 : v);
}

// ---------------- fused setup: zero accum + dtype detect + weight packing ------
__global__ void k_setup(const float* __restrict__ wl1, const float* __restrict__ wr1,
                        const float* __restrict__ wl2, const float* __restrict__ wr2,
                        const int* __restrict__ ei) {
    int i = blockIdx.x * 256 + threadIdx.x;
    if (i < 512 * 128) {                     // pack B1 [w1_l | w1_r] -> tf32
        int k = i >> 7, j = i & 127;
        float v = (j < 64) ? wl1[k * 64 + j] : wr1[k * 64 + (j - 64)];
        g_B1[i] = f2tf32(v);
    }
    if (i < 128 * 128) {                     // pack B2 [[w2_l];[w2_r]] -> tf32
        int k = i >> 7, j = i & 127;
        float v = (k < 64) ? wl2[k * 128 + j] : wr2[(k - 64) * 128 + j];
        g_B2[i] = f2tf32(v);
    }
    if (i < NN)        g_deg[i] = 0;
    if (i < NG * HD2)  g_pooled[i] = 0.f;
    if (i < NG)        g_cnt[i] = 0;
    if (i == 0) {                            // int64 LE => odd int32 words all 0
        int odd_or = 0;
        for (int q = 0; q < 256; q++) odd_or |= ei[2 * q + 1];
        g_is64 = (odd_or == 0) ? 1 : 0;
    }
}

// ---------------- CSR build (dtype-agnostic index loads) -----------------------
__device__ __forceinline__ int load_src(const int* ei, int e, int is64) {
    return is64 ? ei[2 * e] : ei[e];
}
__device__ __forceinline__ int load_dst(const int* ei, int e, int is64) {
    return is64 ? ei[2 * (NE + e)] : ei[NE + e];
}

__global__ void k_deg(const int* __restrict__ ei) {
    int e = blockIdx.x * 256 + threadIdx.x;
    if (e >= NE) return;
    int is64 = g_is64;
    int d = clampN(load_dst(ei, e, is64), NN);
    atomicAdd(&g_deg[d], 1);
}

__global__ void k_scan() {
    __shared__ int sums[1024];
    const int t = threadIdx.x;
    const int chunk = (NN + 1023) >> 10;          // 49
    int beg = t * chunk, end = beg + chunk;
    if (end > NN) end = NN;
    if (beg > NN) beg = NN;
    int s = 0;
    for (int i = beg; i < end; i++) s += g_deg[i];
    sums[t] = s;
    __syncthreads();
    for (int off = 1; off < 1024; off <<= 1) {
        int v = (t >= off) ? sums[t - off] : 0;
        __syncthreads();
        sums[t] += v;
        __syncthreads();
    }
    int run = sums[t] - s;                        // exclusive prefix for this chunk
    for (int i = beg; i < end; i++) {
        g_rowstart[i] = run;
        g_cursor[i]   = run;
        run += g_deg[i];
    }
    if (t == 1023) g_rowstart[NN] = sums[1023];
}

__global__ void k_fill(const int* __restrict__ ei) {
    int e = blockIdx.x * 256 + threadIdx.x;
    if (e >= NE) return;
    int is64 = g_is64;
    int s = clampN(load_src(ei, e, is64), NN);
    int d = clampN(load_dst(ei, e, is64), NN);
    int pos = atomicAdd(&g_cursor[d], 1);
    if (pos >= 0 && pos < NE) g_csrsrc[pos] = s;
}

// ---------------- tf32 tensor-core GEMM, cp.async double-buffered --------------
// C[M,128] = A[M,K] @ B[K,128] (+bias). BM=128, BN=128, BK=32, 256 threads.
// SMEM: A raw f32 bits [buf][128 rows][36] (144B rows, 16B-aligned, conflict-free:
//       36 mod 32 = 4 -> addr = 4g+t distinct). tf32 rounding applied after LDS.
//       B tf32 [buf][32 k][136]  (544B rows; 136 mod 32 = 8 -> 8t+g distinct).
#define GEMM_SMEM_BYTES ((2 * 128 * 36 + 2 * 32 * 136) * 4)   // 71680

template <int K>
__global__ __launch_bounds__(256)
void gemm_db(const float* __restrict__ A, const unsigned* __restrict__ B,
             const float* __restrict__ bias, float* __restrict__ C, int M) {
    extern __shared__ __align__(16) unsigned smem[];
    unsigned* As = smem;                       // 2 * 128*36
    unsigned* Bs = smem + 2 * 128 * 36;        // 2 * 32*136
    const int ASTR = 36, ABUF = 128 * 36;
    const int BSTR = 136, BBUF = 32 * 136;

    const int tid  = threadIdx.x;
    const int wid  = tid >> 5;
    const int lane = tid & 31;
    const int g    = lane >> 2;
    const int t    = lane & 3;
    const int warpM = wid & 3, warpN = wid >> 2;
    const int rowBase = warpM * 32, colBase = warpN * 64;
    const int blockRow = blockIdx.x * 128;

    // A staging map: thread -> (row = tid>>1, half = tid&1), 4x16B each
    const int arow = tid >> 1, ahalf = tid & 1;
    int agr = blockRow + arow; if (agr >= M) agr = M - 1;     // clamp; tail never stored
    const float* aSrc = A + (size_t)agr * K + ahalf * 16;
    const unsigned aDst = arow * ASTR + ahalf * 16;
    // B staging map: thread -> (row = tid>>3, seg = tid&7), 4x16B each
    const int brow = tid >> 3, bseg = tid & 7;
    const unsigned* bSrc = B + brow * 128 + bseg * 16;
    const unsigned bDst = brow * BSTR + bseg * 16;

    float acc[2][8][4];
#pragma unroll
    for (int mi = 0; mi < 2; mi++)
#pragma unroll
        for (int ni = 0; ni < 8; ni++)
#pragma unroll
            for (int r = 0; r < 4; r++) acc[mi][ni][r] = 0.f;

    constexpr int NT = K / 32;

    // prologue: stage tile 0 into buf 0
    {
        unsigned* ad = As + aDst;
#pragma unroll
        for (int j = 0; j < 4; j++) cp16(ad + j * 4, aSrc + j * 4);
        unsigned* bd = Bs + bDst;
#pragma unroll
        for (int j = 0; j < 4; j++) cp16(bd + j * 4, bSrc + j * 4);
        asm volatile("cp.async.commit_group;" ::: "memory");
    }

    int cur = 0;
    for (int ti = 0; ti < NT; ti++) {
        if (ti + 1 < NT) {       // stage next tile into other buffer
            int kt = (ti + 1) * 32;
            unsigned* ad = As + (cur ^ 1) * ABUF + aDst;
            const float* asrc = aSrc + kt;
#pragma unroll
            for (int j = 0; j < 4; j++) cp16(ad + j * 4, asrc + j * 4);
            unsigned* bd = Bs + (cur ^ 1) * BBUF + bDst;
            const unsigned* bsrc = bSrc + (size_t)kt * 128;
#pragma unroll
            for (int j = 0; j < 4; j++) cp16(bd + j * 4, bsrc + j * 4);
            asm volatile("cp.async.commit_group;" ::: "memory");
            asm volatile("cp.async.wait_group 1;" ::: "memory");
        } else {
            asm volatile("cp.async.wait_group 0;" ::: "memory");
        }
        __syncthreads();

        const unsigned* Ab = As + cur * ABUF;
        const unsigned* Bb = Bs + cur * BBUF;
#pragma unroll
        for (int kk = 0; kk < 4; kk++) {
            const int k0 = kk * 8;
            unsigned a[2][4];
#pragma unroll
            for (int mi = 0; mi < 2; mi++) {
                int r = rowBase + mi * 16 + g;
                a[mi][0] = u2tf32(Ab[r       * ASTR + k0 + t]);
                a[mi][1] = u2tf32(Ab[(r + 8) * ASTR + k0 + t]);
                a[mi][2] = u2tf32(Ab[r       * ASTR + k0 + t + 4]);
                a[mi][3] = u2tf32(Ab[(r + 8) * ASTR + k0 + t + 4]);
            }
            unsigned b[8][2];
#pragma unroll
            for (int ni = 0; ni < 8; ni++) {
                int c = colBase + ni * 8 + g;
                b[ni][0] = Bb[(k0 + t)     * BSTR + c];
                b[ni][1] = Bb[(k0 + t + 4) * BSTR + c];
            }
#pragma unroll
            for (int mi = 0; mi < 2; mi++)
#pragma unroll
                for (int ni = 0; ni < 8; ni++)
                    asm volatile(
                        "mma.sync.aligned.m16n8k8.row.col.f32.tf32.tf32.f32 "
                        "{%0,%1,%2,%3}, {%4,%5,%6,%7}, {%8,%9}, {%0,%1,%2,%3};\n"
                        : "+f"(acc[mi][ni][0]), "+f"(acc[mi][ni][1]),
                          "+f"(acc[mi][ni][2]), "+f"(acc[mi][ni][3])
                        : "r"(a[mi][0]), "r"(a[mi][1]), "r"(a[mi][2]), "r"(a[mi][3]),
                          "r"(b[ni][0]), "r"(b[ni][1]));
        }
        cur ^= 1;
        __syncthreads();   // protect buffer reuse by next iteration's cp.async
    }

    // epilogue
#pragma unroll
    for (int mi = 0; mi < 2; mi++) {
        int r0 = blockRow + rowBase + mi * 16 + g;
#pragma unroll
        for (int ni = 0; ni < 8; ni++) {
            int c = colBase + ni * 8 + 2 * t;
            float bx = 0.f, by = 0.f;
            if (bias) { bx = bias[c]; by = bias[c + 1]; }
            if (r0 < M)
                *(float2*)(C + (size_t)r0 * 128 + c) =
                    make_float2(acc[mi][ni][0] + bx, acc[mi][ni][1] + by);
            if (r0 + 8 < M)
                *(float2*)(C + (size_t)(r0 + 8) * 128 + c) =
                    make_float2(acc[mi][ni][2] + bx, acc[mi][ni][3] + by);
        }
    }
}

// ---------------- layer-1 combine: h = relu(mean(agg y_l) + b1 + y_r) ----------
__global__ void k_agg1(const float* __restrict__ y, const float* __restrict__ b1,
                       float* __restrict__ h) {
    int node = blockIdx.x * 8 + (threadIdx.x >> 5);
    if (node >= NN) return;
    int lane = threadIdx.x & 31;
    int beg = g_rowstart[node], end = g_rowstart[node + 1];
    float ax = 0.f, ay = 0.f;
    int e = beg;
    for (; e + 1 < end; e += 2) {            // 2-way unroll for MLP
        int s0 = g_csrsrc[e], s1 = g_csrsrc[e + 1];
        float2 v0 = *(const float2*)(y + (size_t)s0 * 128 + 2 * lane);
        float2 v1 = *(const float2*)(y + (size_t)s1 * 128 + 2 * lane);
        ax += v0.x + v1.x; ay += v0.y + v1.y;
    }
    if (e < end) {
        int s = g_csrsrc[e];
        float2 v = *(const float2*)(y + (size_t)s * 128 + 2 * lane);
        ax += v.x; ay += v.y;
    }
    float inv = 1.f / fmaxf((float)(end - beg), 1.f);
    float2 yr = *(const float2*)(y + (size_t)node * 128 + 64 + 2 * lane);
    float b0 = b1[2 * lane], b1v = b1[2 * lane + 1];
    float o0 = fmaxf(ax * inv + b0 + yr.x, 0.f);
    float o1 = fmaxf(ay * inv + b1v + yr.y, 0.f);
    *(float2*)(h + (size_t)node * 64 + 2 * lane) = make_float2(o0, o1);
}

// ---------------- layer-2 input: g = [mean(agg h) | h] -------------------------
__global__ void k_agg2(const float* __restrict__ h, float* __restrict__ gbuf) {
    int node = blockIdx.x * 8 + (threadIdx.x >> 5);
    if (node >= NN) return;
    int lane = threadIdx.x & 31;
    int beg = g_rowstart[node], end = g_rowstart[node + 1];
    float ax = 0.f, ay = 0.f;
    int e = beg;
    for (; e + 1 < end; e += 2) {
        int s0 = g_csrsrc[e], s1 = g_csrsrc[e + 1];
        float2 v0 = *(const float2*)(h + (size_t)s0 * 64 + 2 * lane);
        float2 v1 = *(const float2*)(h + (size_t)s1 * 64 + 2 * lane);
        ax += v0.x + v1.x; ay += v0.y + v1.y;
    }
    if (e < end) {
        int s = g_csrsrc[e];
        float2 v = *(const float2*)(h + (size_t)s * 64 + 2 * lane);
        ax += v.x; ay += v.y;
    }
    float inv = 1.f / fmaxf((float)(end - beg), 1.f);
    float2 hv = *(const float2*)(h + (size_t)node * 64 + 2 * lane);
    *(float2*)(gbuf + (size_t)node * 128 + 2 * lane)      = make_float2(ax * inv, ay * inv);
    *(float2*)(gbuf + (size_t)node * 128 + 64 + 2 * lane) = hv;
}

// ---------------- global mean pool (batch is sorted) ---------------------------
__global__ void k_pool(const float* __restrict__ h2, const int* __restrict__ batch) {
    int f = threadIdx.x;                    // 128 features
    int is64 = g_is64;
    int start = blockIdx.x * 128;
    int end = start + 128; if (end > NN) end = NN;
    float acc = 0.f;
    int cur = -1, cl = 0;
    for (int i = start; i < end; i++) {
        int gg = clampN(is64 ? batch[2 * i] : batch[i], NG);
        if (gg != cur) {
            if (cur >= 0) {
                atomicAdd(&g_pooled[cur * 128 + f], acc);
                if (f == 0) atomicAdd(&g_cnt[cur], cl);
            }
            cur = gg; acc = 0.f; cl = 0;
        }
        acc += h2[(size_t)i * 128 + f];
        cl++;
    }
    if (cur >= 0) {
        atomicAdd(&g_pooled[cur * 128 + f], acc);
        if (f == 0) atomicAdd(&g_cnt[cur], cl);
    }
}

// ---------------- final FC + log_softmax --------------------------------------
__global__ void k_final(const float* __restrict__ wfc, const float* __restrict__ bfc,
                        float* __restrict__ out) {
    int gi = threadIdx.x;
    if (gi >= NG) return;
    float invc = 1.f / fmaxf((float)g_cnt[gi], 1.f);
    float z[NC];
#pragma unroll
    for (int c = 0; c < NC; c++) z[c] = bfc[c];
    for (int k = 0; k < HD2; k++) {
        float p = g_pooled[gi * HD2 + k] * invc;
#pragma unroll
        for (int c = 0; c < NC; c++) z[c] += p * wfc[k * NC + c];
    }
    float m = z[0];
#pragma unroll
    for (int c = 1; c < NC; c++) m = fmaxf(m, z[c]);
    float s = 0.f;
#pragma unroll
    for (int c = 0; c < NC; c++) s += expf(z[c] - m);
    float lse = m + logf(s);
#pragma unroll
    for (int c = 0; c < NC; c++) out[gi * NC + c] = z[c] - lse;
}

// ---------------- launch -------------------------------------------------------
extern "C" void kernel_launch(void* const* d_in, const int* in_sizes, int n_in,
                              void* d_out, int out_size) {
    const float* x     = (const float*)d_in[0];
    const int*   ei    = (const int*)d_in[1];    // int32 OR int64 (runtime-detected)
    const int*   batch = (const int*)d_in[2];
    const float* w1l   = (const float*)d_in[3];
    const float* b1    = (const float*)d_in[4];
    const float* w1r   = (const float*)d_in[5];
    const float* w2l   = (const float*)d_in[6];
    const float* b2    = (const float*)d_in[7];
    const float* w2r   = (const float*)d_in[8];
    const float* wfc   = (const float*)d_in[9];
    const float* bfc   = (const float*)d_in[10];
    float* out = (float*)d_out;

    float *buf1, *buf2, *hbuf;
    unsigned *B1, *B2;
    cudaGetSymbolAddress((void**)&buf1, g_buf1);
    cudaGetSymbolAddress((void**)&buf2, g_buf2);
    cudaGetSymbolAddress((void**)&hbuf, g_h);
    cudaGetSymbolAddress((void**)&B1,   g_B1);
    cudaGetSymbolAddress((void**)&B2,   g_B2);

    cudaFuncSetAttribute(gemm_db<512>, cudaFuncAttributeMaxDynamicSharedMemorySize,
                         GEMM_SMEM_BYTES);
    cudaFuncSetAttribute(gemm_db<128>, cudaFuncAttributeMaxDynamicSharedMemorySize,
                         GEMM_SMEM_BYTES);

    k_setup<<<256, 256>>>(w1l, w1r, w2l, w2r, ei);
    k_deg<<<(NE + 255) / 256, 256>>>(ei);
    k_scan<<<1, 1024>>>();
    k_fill<<<(NE + 255) / 256, 256>>>(ei);

    gemm_db<512><<<(NN + 127) / 128, 256, GEMM_SMEM_BYTES>>>(x, B1, nullptr, buf1, NN);
    k_agg1<<<(NN + 7) / 8, 256>>>(buf1, b1, hbuf);
    k_agg2<<<(NN + 7) / 8, 256>>>(hbuf, buf2);
    gemm_db<128><<<(NN + 127) / 128, 256, GEMM_SMEM_BYTES>>>(buf2, B2, b2, buf1, NN);

    k_pool<<<(NN + 127) / 128, 128>>>(buf1, batch);
    k_final<<<1, 64>>>(wfc, bfc, out);
}

// round 12
// speedup vs baseline: 1.1220x; 1.0410x over previous
#include <cuda_runtime.h>
#include <cuda_bf16.h>
#include <cstdint>
#include <math.h>

#define NN 50000
#define NE 800000
#define FIN 512
#define HD1 64
#define HD2 128
#define NG 64
#define NC 10

// ---------------- scratch (device globals; no runtime allocation) -------------
__device__ __align__(16) float    g_buf1[(size_t)NN * 128]; // GEMM out; reused as h2
__device__ __align__(16) float    g_buf2[(size_t)NN * 64];  // layer-2 mean_h (64-wide)
__device__ __align__(16) float    g_h   [(size_t)NN * 64];  // layer-1 activations
__device__ __align__(16) unsigned g_B1t [128 * 512];        // tf32 [w1_l|w1_r]^T : [n][k]
__device__ __align__(16) unsigned g_B2t [128 * 128];        // tf32 [[w2_l];[w2_r]]^T : [n][k]
__device__ int      g_deg [NN];
__device__ int      g_rowstart[NN + 1];
__device__ int      g_cursor[NN];
__device__ __align__(16) int g_csrsrc[NE];
__device__ float    g_pooled[NG * HD2];
__device__ int      g_cnt [NG];
__device__ int      g_is64;   // 1 if edge_index/batch are int64, 0 if int32

__device__ __forceinline__ unsigned f2tf32(float x) {
    unsigned r;
    asm("cvt.rna.tf32.f32 %0, %1;" : "=r"(r) : "f"(x));
    return r;
}
__device__ __forceinline__ unsigned u2tf32(unsigned ub) {
    unsigned r; float f = __uint_as_float(ub);
    asm("cvt.rna.tf32.f32 %0, %1;" : "=r"(r) : "f"(f));
    return r;
}
__device__ __forceinline__ void cp16(unsigned* dst_smem, const void* src) {
    unsigned d = (unsigned)__cvta_generic_to_shared(dst_smem);
    asm volatile("cp.async.cg.shared.global [%0], [%1], 16;" :: "r"(d), "l"(src) : "memory");
}
__device__ __forceinline__ void ldm4(const unsigned* p, unsigned& r0, unsigned& r1,
                                     unsigned& r2, unsigned& r3) {
    unsigned a = (unsigned)__cvta_generic_to_shared(p);
    asm volatile("ldmatrix.sync.aligned.m8n8.x4.shared.b16 {%0,%1,%2,%3}, [%4];"
                 : "=r"(r0), "=r"(r1), "=r"(r2), "=r"(r3) : "r"(a));
}
__device__ __forceinline__ int clampN(int v, int n) {
    return (v < 0) ? 0 : (v >= n ? n - 1 : v);
}

// ---------------- fused setup: zero accum + dtype detect + transposed packing --
__global__ void k_setup(const float* __restrict__ wl1, const float* __restrict__ wr1,
                        const float* __restrict__ wl2, const float* __restrict__ wr2,
                        const int* __restrict__ ei) {
    int i = blockIdx.x * 256 + threadIdx.x;
    if (i < 512 * 128) {                     // B1t[j][k] = ([w1_l|w1_r])(k,j), tf32
        int k = i >> 7, j = i & 127;
        float v = (j < 64) ? wl1[k * 64 + j] : wr1[k * 64 + (j - 64)];
        g_B1t[j * 512 + k] = f2tf32(v);
    }
    if (i < 128 * 128) {                     // B2t[j][k] = ([[w2_l];[w2_r]])(k,j), tf32
        int k = i >> 7, j = i & 127;
        float v = (k < 64) ? wl2[k * 128 + j] : wr2[(k - 64) * 128 + j];
        g_B2t[j * 128 + k] = f2tf32(v);
    }
    if (i < NN)        g_deg[i] = 0;
    if (i < NG * HD2)  g_pooled[i] = 0.f;
    if (i < NG)        g_cnt[i] = 0;
    if (i == 0) {                            // int64 LE => odd int32 words all 0
        int odd_or = 0;
        for (int q = 0; q < 256; q++) odd_or |= ei[2 * q + 1];
        g_is64 = (odd_or == 0) ? 1 : 0;
    }
}

// ---------------- CSR build ----------------------------------------------------
__global__ void k_deg(const int* __restrict__ ei) {
    int is64 = g_is64;
    if (!is64) {
        int e4 = (blockIdx.x * 256 + threadIdx.x) * 4;
        if (e4 >= NE) return;
        int4 d = *(const int4*)(ei + NE + e4);
        atomicAdd(&g_deg[clampN(d.x, NN)], 1);
        atomicAdd(&g_deg[clampN(d.y, NN)], 1);
        atomicAdd(&g_deg[clampN(d.z, NN)], 1);
        atomicAdd(&g_deg[clampN(d.w, NN)], 1);
    } else {
        int e4 = (blockIdx.x * 256 + threadIdx.x) * 4;
        for (int e = e4; e < e4 + 4 && e < NE; e++)
            atomicAdd(&g_deg[clampN(ei[2 * (NE + e)], NN)], 1);
    }
}

__global__ void k_scan() {
    __shared__ int sums[1024];
    const int t = threadIdx.x;
    const int chunk = (NN + 1023) >> 10;          // 49
    int beg = t * chunk, end = beg + chunk;
    if (end > NN) end = NN;
    if (beg > NN) beg = NN;
    int s = 0;
    for (int i = beg; i < end; i++) s += g_deg[i];
    sums[t] = s;
    __syncthreads();
    for (int off = 1; off < 1024; off <<= 1) {
        int v = (t >= off) ? sums[t - off] : 0;
        __syncthreads();
        sums[t] += v;
        __syncthreads();
    }
    int run = sums[t] - s;                        // exclusive prefix for this chunk
    for (int i = beg; i < end; i++) {
        g_rowstart[i] = run;
        g_cursor[i]   = run;
        run += g_deg[i];
    }
    if (t == 1023) g_rowstart[NN] = sums[1023];
}

__global__ void k_fill(const int* __restrict__ ei) {
    int is64 = g_is64;
    if (!is64) {
        int e4 = (blockIdx.x * 256 + threadIdx.x) * 4;
        if (e4 >= NE) return;
        int4 s = *(const int4*)(ei + e4);
        int4 d = *(const int4*)(ei + NE + e4);
        int p;
        p = atomicAdd(&g_cursor[clampN(d.x, NN)], 1); if (p >= 0 && p < NE) g_csrsrc[p] = clampN(s.x, NN);
        p = atomicAdd(&g_cursor[clampN(d.y, NN)], 1); if (p >= 0 && p < NE) g_csrsrc[p] = clampN(s.y, NN);
        p = atomicAdd(&g_cursor[clampN(d.z, NN)], 1); if (p >= 0 && p < NE) g_csrsrc[p] = clampN(s.z, NN);
        p = atomicAdd(&g_cursor[clampN(d.w, NN)], 1); if (p >= 0 && p < NE) g_csrsrc[p] = clampN(s.w, NN);
    } else {
        int e4 = (blockIdx.x * 256 + threadIdx.x) * 4;
        for (int e = e4; e < e4 + 4 && e < NE; e++) {
            int s = clampN(ei[2 * e], NN);
            int d = clampN(ei[2 * (NE + e)], NN);
            int p = atomicAdd(&g_cursor[d], 1);
            if (p >= 0 && p < NE) g_csrsrc[p] = s;
        }
    }
}

// ---------------- tf32 GEMM: ldmatrix frags + cp.async double buffer -----------
// C[M,128] = [A0|A1][M,K] @ Bt^T (+bias).  A row-major raw f32 (cvt after LDSM);
// Bt is [128 n][K] tf32.  BM=128, BN=128, BK=32, 256 threads, warp tile 32x64.
// SMEM tiles [128 rows][36 words] (144B rows): ldmatrix conflict-free.
#define GEMM_SMEM_BYTES (4 * 128 * 36 * 4)   // 73728

template <int K, int SPLIT>
__global__ __launch_bounds__(256, 2)
void gemm_lm(const float* __restrict__ A0, const float* __restrict__ A1,
             const unsigned* __restrict__ Bt, const float* __restrict__ bias,
             float* __restrict__ C, int M) {
    extern __shared__ __align__(16) unsigned smem[];
    const int STR = 36, TBUF = 128 * 36;
    unsigned* As = smem;              // [2][128][36]
    unsigned* Bs = smem + 2 * TBUF;   // [2][128][36]

    const int tid = threadIdx.x;
    const int wid = tid >> 5, lane = tid & 31;
    const int g = lane >> 2, t = lane & 3;
    const int warpM = wid & 3, warpN = wid >> 2;
    const int rowBase = warpM * 32, colBase = warpN * 64;
    const int blockRow = blockIdx.x * 128;

    // staging: thread -> (row tid>>1, 16-float half tid&1) for both A and B
    const int srow = tid >> 1, shalf = tid & 1;
    int agr = blockRow + srow; if (agr >= M) agr = M - 1;   // clamp; tail never stored
    const unsigned sDst = srow * STR + shalf * 16;
    const unsigned* bSrcBase = Bt + (size_t)srow * K + shalf * 16;

    // ldmatrix per-lane address components
    const int aRow = (lane & 7) + ((lane >> 3) & 1) * 8;
    const int aCol = ((lane >> 4) & 1) * 4;
    const int bRow = (lane & 7) + ((lane >> 4) & 1) * 8;
    const int bCol = ((lane >> 3) & 1) * 4;

    float acc[2][8][4];
#pragma unroll
    for (int mi = 0; mi < 2; mi++)
#pragma unroll
        for (int ni = 0; ni < 8; ni++)
#pragma unroll
            for (int r = 0; r < 4; r++) acc[mi][ni][r] = 0.f;

    constexpr int NT = K / 32;

    auto stage = [&](int kt, int buf) {
        const float* asrc = (kt < SPLIT)
            ? (A0 + (size_t)agr * SPLIT + kt + shalf * 16)
            : (A1 + (size_t)agr * (K - SPLIT) + (kt - SPLIT) + shalf * 16);
        unsigned* ad = As + buf * TBUF + sDst;
#pragma unroll
        for (int j = 0; j < 4; j++) cp16(ad + j * 4, asrc + j * 4);
        const unsigned* bsrc = bSrcBase + kt;
        unsigned* bd = Bs + buf * TBUF + sDst;
#pragma unroll
        for (int j = 0; j < 4; j++) cp16(bd + j * 4, bsrc + j * 4);
        asm volatile("cp.async.commit_group;" ::: "memory");
    };

    stage(0, 0);

    int cur = 0;
    for (int ti = 0; ti < NT; ti++) {
        if (ti + 1 < NT) {
            stage((ti + 1) * 32, cur ^ 1);
            asm volatile("cp.async.wait_group 1;" ::: "memory");
        } else {
            asm volatile("cp.async.wait_group 0;" ::: "memory");
        }
        __syncthreads();

        const unsigned* Ab = As + cur * TBUF;
        const unsigned* Bb = Bs + cur * TBUF;
#pragma unroll
        for (int kk = 0; kk < 4; kk++) {
            const int k0 = kk * 8;
            unsigned a[2][4];
#pragma unroll
            for (int mi = 0; mi < 2; mi++) {
                ldm4(Ab + (rowBase + mi * 16 + aRow) * STR + k0 + aCol,
                     a[mi][0], a[mi][1], a[mi][2], a[mi][3]);
                a[mi][0] = u2tf32(a[mi][0]); a[mi][1] = u2tf32(a[mi][1]);
                a[mi][2] = u2tf32(a[mi][2]); a[mi][3] = u2tf32(a[mi][3]);
            }
            unsigned b[8][2];
#pragma unroll
            for (int nip = 0; nip < 4; nip++) {
                ldm4(Bb + (colBase + nip * 16 + bRow) * STR + k0 + bCol,
                     b[2 * nip][0], b[2 * nip][1], b[2 * nip + 1][0], b[2 * nip + 1][1]);
            }
#pragma unroll
            for (int mi = 0; mi < 2; mi++)
#pragma unroll
                for (int ni = 0; ni < 8; ni++)
                    asm volatile(
                        "mma.sync.aligned.m16n8k8.row.col.f32.tf32.tf32.f32 "
                        "{%0,%1,%2,%3}, {%4,%5,%6,%7}, {%8,%9}, {%0,%1,%2,%3};\n"
                        : "+f"(acc[mi][ni][0]), "+f"(acc[mi][ni][1]),
                          "+f"(acc[mi][ni][2]), "+f"(acc[mi][ni][3])
                        : "r"(a[mi][0]), "r"(a[mi][1]), "r"(a[mi][2]), "r"(a[mi][3]),
                          "r"(b[ni][0]), "r"(b[ni][1]));
        }
        cur ^= 1;
        __syncthreads();   // protect buffer reuse by next iteration's cp.async
    }

    // epilogue
#pragma unroll
    for (int mi = 0; mi < 2; mi++) {
        int r0 = blockRow + rowBase + mi * 16 + g;
#pragma unroll
        for (int ni = 0; ni < 8; ni++) {
            int c = colBase + ni * 8 + 2 * t;
            float bx = 0.f, by = 0.f;
            if (bias) { bx = bias[c]; by = bias[c + 1]; }
            if (r0 < M)
                *(float2*)(C + (size_t)r0 * 128 + c) =
                    make_float2(acc[mi][ni][0] + bx, acc[mi][ni][1] + by);
            if (r0 + 8 < M)
                *(float2*)(C + (size_t)(r0 + 8) * 128 + c) =
                    make_float2(acc[mi][ni][2] + bx, acc[mi][ni][3] + by);
        }
    }
}

// ---------------- layer-1 combine: h = relu(mean(agg y_l) + b1 + y_r) ----------
// warp per node; half-warps process alternate edges; float4 per lane (16 lanes x 4 = 64 feats)
__global__ void k_agg1(const float* __restrict__ y, const float* __restrict__ b1,
                       float* __restrict__ h) {
    int node = blockIdx.x * 8 + (threadIdx.x >> 5);
    if (node >= NN) return;
    int lane = threadIdx.x & 31;
    int half = lane >> 4, fl = lane & 15;
    int beg = g_rowstart[node], end = g_rowstart[node + 1];
    float4 acc = make_float4(0.f, 0.f, 0.f, 0.f);
    for (int e = beg + half; e < end; e += 2) {
        int s = g_csrsrc[e];
        float4 v = *(const float4*)(y + (size_t)s * 128 + fl * 4);
        acc.x += v.x; acc.y += v.y; acc.z += v.z; acc.w += v.w;
    }
    acc.x += __shfl_xor_sync(0xffffffffu, acc.x, 16);
    acc.y += __shfl_xor_sync(0xffffffffu, acc.y, 16);
    acc.z += __shfl_xor_sync(0xffffffffu, acc.z, 16);
    acc.w += __shfl_xor_sync(0xffffffffu, acc.w, 16);
    if (half == 0) {
        float inv = 1.f / fmaxf((float)(end - beg), 1.f);
        float4 yr = *(const float4*)(y + (size_t)node * 128 + 64 + fl * 4);
        float4 bb = *(const float4*)(b1 + fl * 4);
        float4 o;
        o.x = fmaxf(acc.x * inv + bb.x + yr.x, 0.f);
        o.y = fmaxf(acc.y * inv + bb.y + yr.y, 0.f);
        o.z = fmaxf(acc.z * inv + bb.z + yr.z, 0.f);
        o.w = fmaxf(acc.w * inv + bb.w + yr.w, 0.f);
        *(float4*)(h + (size_t)node * 64 + fl * 4) = o;
    }
}

// ---------------- layer-2 mean: m = mean(agg h)  (h passed to GEMM2 directly) --
__global__ void k_agg2(const float* __restrict__ h, float* __restrict__ m) {
    int node = blockIdx.x * 8 + (threadIdx.x >> 5);
    if (node >= NN) return;
    int lane = threadIdx.x & 31;
    int half = lane >> 4, fl = lane & 15;
    int beg = g_rowstart[node], end = g_rowstart[node + 1];
    float4 acc = make_float4(0.f, 0.f, 0.f, 0.f);
    for (int e = beg + half; e < end; e += 2) {
        int s = g_csrsrc[e];
        float4 v = *(const float4*)(h + (size_t)s * 64 + fl * 4);
        acc.x += v.x; acc.y += v.y; acc.z += v.z; acc.w += v.w;
    }
    acc.x += __shfl_xor_sync(0xffffffffu, acc.x, 16);
    acc.y += __shfl_xor_sync(0xffffffffu, acc.y, 16);
    acc.z += __shfl_xor_sync(0xffffffffu, acc.z, 16);
    acc.w += __shfl_xor_sync(0xffffffffu, acc.w, 16);
    if (half == 0) {
        float inv = 1.f / fmaxf((float)(end - beg), 1.f);
        float4 o = make_float4(acc.x * inv, acc.y * inv, acc.z * inv, acc.w * inv);
        *(float4*)(m + (size_t)node * 64 + fl * 4) = o;
    }
}

// ---------------- global mean pool (batch is sorted) ---------------------------
__global__ void k_pool(const float* __restrict__ h2, const int* __restrict__ batch) {
    int f = threadIdx.x;                    // 128 features
    int is64 = g_is64;
    int start = blockIdx.x * 128;
    int end = start + 128; if (end > NN) end = NN;
    float acc = 0.f;
    int cur = -1, cl = 0;
    for (int i = start; i < end; i++) {
        int gg = clampN(is64 ? batch[2 * i] : batch[i], NG);
        if (gg != cur) {
            if (cur >= 0) {
                atomicAdd(&g_pooled[cur * 128 + f], acc);
                if (f == 0) atomicAdd(&g_cnt[cur], cl);
            }
            cur = gg; acc = 0.f; cl = 0;
        }
        acc += h2[(size_t)i * 128 + f];
        cl++;
    }
    if (cur >= 0) {
        atomicAdd(&g_pooled[cur * 128 + f], acc);
        if (f == 0) atomicAdd(&g_cnt[cur], cl);
    }
}

// ---------------- final FC + log_softmax --------------------------------------
__global__ void k_final(const float* __restrict__ wfc, const float* __restrict__ bfc,
                        float* __restrict__ out) {
    int gi = threadIdx.x;
    if (gi >= NG) return;
    float invc = 1.f / fmaxf((float)g_cnt[gi], 1.f);
    float z[NC];
#pragma unroll
    for (int c = 0; c < NC; c++) z[c] = bfc[c];
    for (int k = 0; k < HD2; k++) {
        float p = g_pooled[gi * HD2 + k] * invc;
#pragma unroll
        for (int c = 0; c < NC; c++) z[c] += p * wfc[k * NC + c];
    }
    float m = z[0];
#pragma unroll
    for (int c = 1; c < NC; c++) m = fmaxf(m, z[c]);
    float s = 0.f;
#pragma unroll
    for (int c = 0; c < NC; c++) s += expf(z[c] - m);
    float lse = m + logf(s);
#pragma unroll
    for (int c = 0; c < NC; c++) out[gi * NC + c] = z[c] - lse;
}

// ---------------- launch -------------------------------------------------------
extern "C" void kernel_launch(void* const* d_in, const int* in_sizes, int n_in,
                              void* d_out, int out_size) {
    const float* x     = (const float*)d_in[0];
    const int*   ei    = (const int*)d_in[1];    // int32 OR int64 (runtime-detected)
    const int*   batch = (const int*)d_in[2];
    const float* w1l   = (const float*)d_in[3];
    const float* b1    = (const float*)d_in[4];
    const float* w1r   = (const float*)d_in[5];
    const float* w2l   = (const float*)d_in[6];
    const float* b2    = (const float*)d_in[7];
    const float* w2r   = (const float*)d_in[8];
    const float* wfc   = (const float*)d_in[9];
    const float* bfc   = (const float*)d_in[10];
    float* out = (float*)d_out;

    float *buf1, *buf2m, *hbuf;
    unsigned *B1t, *B2t;
    cudaGetSymbolAddress((void**)&buf1,  g_buf1);
    cudaGetSymbolAddress((void**)&buf2m, g_buf2);
    cudaGetSymbolAddress((void**)&hbuf,  g_h);
    cudaGetSymbolAddress((void**)&B1t,   g_B1t);
    cudaGetSymbolAddress((void**)&B2t,   g_B2t);

    cudaFuncSetAttribute(gemm_lm<512, 512>, cudaFuncAttributeMaxDynamicSharedMemorySize,
                         GEMM_SMEM_BYTES);
    cudaFuncSetAttribute(gemm_lm<128, 64>, cudaFuncAttributeMaxDynamicSharedMemorySize,
                         GEMM_SMEM_BYTES);

    k_setup<<<256, 256>>>(w1l, w1r, w2l, w2r, ei);
    k_deg<<<(NE / 4 + 255) / 256, 256>>>(ei);
    k_scan<<<1, 1024>>>();
    k_fill<<<(NE / 4 + 255) / 256, 256>>>(ei);

    gemm_lm<512, 512><<<(NN + 127) / 128, 256, GEMM_SMEM_BYTES>>>(x, x, B1t, nullptr, buf1, NN);
    k_agg1<<<(NN + 7) / 8, 256>>>(buf1, b1, hbuf);
    k_agg2<<<(NN + 7) / 8, 256>>>(hbuf, buf2m);
    gemm_lm<128, 64><<<(NN + 127) / 128, 256, GEMM_SMEM_BYTES>>>(buf2m, hbuf, B2t, b2, buf1, NN);

    k_pool<<<(NN + 127) / 128, 128>>>(buf1, batch);
    k_final<<<1, 64>>>(wfc, bfc, out);
}